// round 4
// baseline (speedup 1.0000x reference)
#include <cuda_runtime.h>

#define POOLK 7
#define NUM_ROIS 300
#define FH 50
#define FW 50
#define FC 512

// Scratch: channel-max map (no cudaMalloc allowed)
__device__ float g_fmax[FH * FW];

// Kernel 1: one warp per pixel, max over 512 contiguous channels.
__global__ void fmax_kernel(const float* __restrict__ fm) {
    int warp = (blockIdx.x * blockDim.x + threadIdx.x) >> 5;
    int lane = threadIdx.x & 31;
    if (warp >= FH * FW) return;
    const float4* p = reinterpret_cast<const float4*>(fm + (size_t)warp * FC);
    float m = -INFINITY;
#pragma unroll
    for (int k = 0; k < 4; k++) {
        float4 v = p[lane + 32 * k];
        m = fmaxf(m, fmaxf(fmaxf(v.x, v.y), fmaxf(v.z, v.w)));
    }
#pragma unroll
    for (int off = 16; off > 0; off >>= 1)
        m = fmaxf(m, __shfl_xor_sync(0xffffffffu, m, off));
    if (lane == 0) g_fmax[warp] = m;
}

// Kernel 2: one warp per (roi, bin). Compute bin max over g_fmax, then
// broadcast-write 512 floats (2 KB contiguous) as 4x float4 per lane.
__global__ void roi_kernel(const float* __restrict__ rois,
                           float* __restrict__ out) {
    int warp = (blockIdx.x * blockDim.x + threadIdx.x) >> 5;
    int lane = threadIdx.x & 31;
    if (warp >= NUM_ROIS * POOLK * POOLK) return;

    int r = warp / (POOLK * POOLK);
    int bin = warp - r * (POOLK * POOLK);
    int i = bin / POOLK;          // pooled row
    int j = bin - i * POOLK;      // pooled col

    const float* roi = rois + r * 5;
    // reference: (rois * (1/16)).astype(int32)  -> truncation; inputs >= 0
    int x1 = (int)(__ldg(roi + 1) * 0.0625f);
    int y1 = (int)(__ldg(roi + 2) * 0.0625f);
    int x2 = (int)(__ldg(roi + 3) * 0.0625f);
    int y2 = (int)(__ldg(roi + 4) * 0.0625f);
    int rh = y2 - y1 + 1;
    int rw = x2 - x1 + 1;

    int hs = min(max(y1 + (i * rh) / POOLK, 0), FH);
    int he = min(max(y1 + ((i + 1) * rh + POOLK - 1) / POOLK, 0), FH);
    int ws = min(max(x1 + (j * rw) / POOLK, 0), FW);
    int we = min(max(x1 + ((j + 1) * rw + POOLK - 1) / POOLK, 0), FW);

    int nh = he - hs;
    int nw = we - ws;
    int n = nh * nw;

    float m = -INFINITY;
    for (int t = lane; t < n; t += 32) {
        int dy = t / nw;
        int dx = t - dy * nw;
        m = fmaxf(m, g_fmax[(hs + dy) * FW + (ws + dx)]);
    }
#pragma unroll
    for (int off = 16; off > 0; off >>= 1)
        m = fmaxf(m, __shfl_xor_sync(0xffffffffu, m, off));

    float4 v = make_float4(m, m, m, m);
    float4* o = reinterpret_cast<float4*>(out + (size_t)warp * FC);
#pragma unroll
    for (int k = 0; k < 4; k++)
        o[lane + 32 * k] = v;
}

extern "C" void kernel_launch(void* const* d_in, const int* in_sizes, int n_in,
                              void* d_out, int out_size) {
    const float* rois = (const float*)d_in[0];          // (300, 5)
    const float* feature_maps = (const float*)d_in[1];  // (50, 50, 512)
    float* out = (float*)d_out;                         // (300, 7, 7, 512)

    // Kernel 1: 2500 warps, 8 warps/block
    {
        int warps = FH * FW;
        int threads = 256;
        int blocks = (warps * 32 + threads - 1) / threads;
        fmax_kernel<<<blocks, threads>>>(feature_maps);
    }
    // Kernel 2: 14700 warps, 8 warps/block
    {
        int warps = NUM_ROIS * POOLK * POOLK;
        int threads = 256;
        int blocks = (warps * 32 + threads - 1) / threads;
        roi_kernel<<<blocks, threads>>>(rois, out);
    }
}